// round 7
// baseline (speedup 1.0000x reference)
#include <cuda_runtime.h>
#include <cstdint>

#define N_NODES_MAX 100000
#define HIDDEN 64
#define LUT_N 8192
#define LUT_MIN (-32.0f)
#define LUT_RANGE 64.0f

#define NB 148          // <= SM count -> all blocks co-resident, sw barrier safe
#define TB 256

// Scratch. INVARIANT: g_deg and g_accum are all-zero between kernel_launch
// calls (static zero-init; phase D restores both each call).
__device__ float g_deg[N_NODES_MAX];     // zero between calls
__device__ float g_accum[N_NODES_MAX];   // zero between calls
__device__ float g_px[N_NODES_MAX];      // rsqrt(deg+1)*x
__device__ float g_lut[LUT_N + 2];
__device__ unsigned g_bar_count;         // zero between calls (barrier resets it)
__device__ unsigned g_bar_gen;           // monotonic across calls

__device__ __forceinline__ float tanh_approx(float x) {
    float y;
    asm("tanh.approx.f32 %0, %1;" : "=f"(y) : "f"(x));
    return y;
}

// Software grid barrier. Valid because grid (NB=148) <= #SMs -> co-resident.
__device__ __forceinline__ void grid_barrier() {
    __syncthreads();
    if (threadIdx.x == 0) {
        __threadfence();                              // order my phase's writes
        unsigned gen = *(volatile unsigned*)&g_bar_gen;
        if (atomicAdd(&g_bar_count, 1u) == NB - 1u) {
            g_bar_count = 0u;                         // reset BEFORE release
            __threadfence();
            *(volatile unsigned*)&g_bar_gen = gen + 1u;  // release
        } else {
            while (*(volatile unsigned*)&g_bar_gen == gen) { }
        }
        __threadfence();                              // acquire others' writes
    }
    __syncthreads();
}

__global__ void __launch_bounds__(TB, 1)
fused_kernel(const int* __restrict__ src, const int* __restrict__ dst,
             const float* __restrict__ ew, const float* __restrict__ x,
             float* __restrict__ out, int N, int E, int vec_ok,
             const float* __restrict__ Wz, const float* __restrict__ bz,
             const float* __restrict__ Lz, const float* __restrict__ lbz,
             const float* __restrict__ Wh, const float* __restrict__ bh,
             const float* __restrict__ Lh, const float* __restrict__ lbh,
             const float* __restrict__ Wout, const float* __restrict__ bout) {
    const int tid = blockIdx.x * TB + threadIdx.x;
    const int NT  = NB * TB;

    // ===================== Phase A: LUT build + degree =====================
    {
        // every block folds the tiny matrices (L2-hit broadcast, cheap);
        // each thread then fills at most one LUT entry.
        __shared__ float s_uz[HIDDEN], s_cz[HIDDEN], s_uh[HIDDEN], s_ch[HIDDEN], s_w[HIDDEN];
        __shared__ float s_b0;
        int j = threadIdx.x;
        if (j < HIDDEN) {
            float uz = 0.f, cz = lbz[j], uh = 0.f, ch = lbh[j];
            #pragma unroll 8
            for (int k = 0; k < HIDDEN; k++) {
                float lz = Lz[k * HIDDEN + j];
                float lh = Lh[k * HIDDEN + j];
                uz = fmaf(Wz[k], lz, uz);
                cz = fmaf(bz[k], lz, cz);
                uh = fmaf(Wh[k], lh, uh);
                ch = fmaf(bh[k], lh, ch);
            }
            s_uz[j] = uz; s_cz[j] = cz; s_uh[j] = uh; s_ch[j] = ch;
            s_w[j] = Wout[j];
        }
        if (j == 0) s_b0 = bout[0];
        __syncthreads();

        if (tid <= LUT_N + 1) {
            const float step = LUT_RANGE / (float)LUT_N;
            float a = LUT_MIN + (float)tid * step;
            float acc = s_b0;
            #pragma unroll 8
            for (int jj = 0; jj < HIDDEN; jj++) {
                float tz = tanh_approx(0.5f * fmaf(a, s_uz[jj], s_cz[jj]));
                float th = tanh_approx(fmaf(a, s_uh[jj], s_ch[jj]));
                float h = fmaxf(0.5f * (1.0f - tz) * th, 0.0f);
                acc = fmaf(h, s_w[jj], acc);
            }
            g_lut[tid] = acc;
        }

        // degree accumulation, front-batched 4 quads per iteration
        if (vec_ok) {
            int nvec = E >> 2;
            int i = tid;
            while (i + 3 * NT < nvec) {
                int4   d0 = ((const int4*)dst)[i];
                int4   d1 = ((const int4*)dst)[i + NT];
                int4   d2 = ((const int4*)dst)[i + 2 * NT];
                int4   d3 = ((const int4*)dst)[i + 3 * NT];
                float4 w0 = ((const float4*)ew)[i];
                float4 w1 = ((const float4*)ew)[i + NT];
                float4 w2 = ((const float4*)ew)[i + 2 * NT];
                float4 w3 = ((const float4*)ew)[i + 3 * NT];
                atomicAdd(&g_deg[d0.x], w0.x); atomicAdd(&g_deg[d0.y], w0.y);
                atomicAdd(&g_deg[d0.z], w0.z); atomicAdd(&g_deg[d0.w], w0.w);
                atomicAdd(&g_deg[d1.x], w1.x); atomicAdd(&g_deg[d1.y], w1.y);
                atomicAdd(&g_deg[d1.z], w1.z); atomicAdd(&g_deg[d1.w], w1.w);
                atomicAdd(&g_deg[d2.x], w2.x); atomicAdd(&g_deg[d2.y], w2.y);
                atomicAdd(&g_deg[d2.z], w2.z); atomicAdd(&g_deg[d2.w], w2.w);
                atomicAdd(&g_deg[d3.x], w3.x); atomicAdd(&g_deg[d3.y], w3.y);
                atomicAdd(&g_deg[d3.z], w3.z); atomicAdd(&g_deg[d3.w], w3.w);
                i += 4 * NT;
            }
            while (i < nvec) {
                int4   d0 = ((const int4*)dst)[i];
                float4 w0 = ((const float4*)ew)[i];
                atomicAdd(&g_deg[d0.x], w0.x); atomicAdd(&g_deg[d0.y], w0.y);
                atomicAdd(&g_deg[d0.z], w0.z); atomicAdd(&g_deg[d0.w], w0.w);
                i += NT;
            }
            int base = nvec << 2;
            if (tid < E - base)
                atomicAdd(&g_deg[dst[base + tid]], ew[base + tid]);
        } else {
            for (int e = tid; e < E; e += NT)
                atomicAdd(&g_deg[dst[e]], ew[e]);
        }
    }
    grid_barrier();

    // ===================== Phase B: px = rsqrt(deg+1)*x ====================
    {
        int nvec = N >> 2;
        for (int i = tid; i < nvec; i += NT) {
            float4 d4 = ((const float4*)g_deg)[i];
            float4 x4 = ((const float4*)x)[i];
            float4 px;
            px.x = rsqrtf(d4.x + 1.0f) * x4.x;
            px.y = rsqrtf(d4.y + 1.0f) * x4.y;
            px.z = rsqrtf(d4.z + 1.0f) * x4.z;
            px.w = rsqrtf(d4.w + 1.0f) * x4.w;
            ((float4*)g_px)[i] = px;
        }
        int base = nvec << 2;
        if (tid < N - base) {
            int i = base + tid;
            g_px[i] = rsqrtf(g_deg[i] + 1.0f) * x[i];
        }
    }
    grid_barrier();

    // ===================== Phase C: normalized scatter ======================
    {
        if (vec_ok) {
            int nvec = E >> 2;
            int i = tid;
            while (i + NT < nvec) {   // 2 quads per iter (12 loads in flight)
                int4   s0 = ((const int4*)src)[i];
                int4   s1 = ((const int4*)src)[i + NT];
                int4   d0 = ((const int4*)dst)[i];
                int4   d1 = ((const int4*)dst)[i + NT];
                float4 w0 = ((const float4*)ew)[i];
                float4 w1 = ((const float4*)ew)[i + NT];
                float p00 = __ldg(&g_px[s0.x]), p01 = __ldg(&g_px[s0.y]);
                float p02 = __ldg(&g_px[s0.z]), p03 = __ldg(&g_px[s0.w]);
                float p10 = __ldg(&g_px[s1.x]), p11 = __ldg(&g_px[s1.y]);
                float p12 = __ldg(&g_px[s1.z]), p13 = __ldg(&g_px[s1.w]);
                atomicAdd(&g_accum[d0.x], w0.x * p00);
                atomicAdd(&g_accum[d0.y], w0.y * p01);
                atomicAdd(&g_accum[d0.z], w0.z * p02);
                atomicAdd(&g_accum[d0.w], w0.w * p03);
                atomicAdd(&g_accum[d1.x], w1.x * p10);
                atomicAdd(&g_accum[d1.y], w1.y * p11);
                atomicAdd(&g_accum[d1.z], w1.z * p12);
                atomicAdd(&g_accum[d1.w], w1.w * p13);
                i += 2 * NT;
            }
            while (i < nvec) {
                int4   s0 = ((const int4*)src)[i];
                int4   d0 = ((const int4*)dst)[i];
                float4 w0 = ((const float4*)ew)[i];
                float p00 = __ldg(&g_px[s0.x]), p01 = __ldg(&g_px[s0.y]);
                float p02 = __ldg(&g_px[s0.z]), p03 = __ldg(&g_px[s0.w]);
                atomicAdd(&g_accum[d0.x], w0.x * p00);
                atomicAdd(&g_accum[d0.y], w0.y * p01);
                atomicAdd(&g_accum[d0.z], w0.z * p02);
                atomicAdd(&g_accum[d0.w], w0.w * p03);
                i += NT;
            }
            int base = nvec << 2;
            if (tid < E - base) {
                int e = base + tid;
                atomicAdd(&g_accum[dst[e]], ew[e] * __ldg(&g_px[src[e]]));
            }
        } else {
            for (int e = tid; e < E; e += NT)
                atomicAdd(&g_accum[dst[e]], ew[e] * __ldg(&g_px[src[e]]));
        }
    }
    grid_barrier();

    // ============ Phase D: LUT epilogue; reset g_deg & g_accum =============
    {
        const float inv_step = (float)LUT_N / LUT_RANGE;
        const float4 z4 = make_float4(0.f, 0.f, 0.f, 0.f);
        int nvec = N >> 2;
        for (int i = tid; i < nvec; i += NT) {
            float4 d4  = ((const float4*)g_deg)[i];
            float4 ac4 = ((const float4*)g_accum)[i];
            float4 x4  = ((const float4*)x)[i];
            ((float4*)g_deg)[i]   = z4;     // restore invariant
            ((float4*)g_accum)[i] = z4;     // restore invariant
            float a[4], r[4];
            float di;
            di = rsqrtf(d4.x + 1.0f); a[0] = di * (ac4.x + di * x4.x);
            di = rsqrtf(d4.y + 1.0f); a[1] = di * (ac4.y + di * x4.y);
            di = rsqrtf(d4.z + 1.0f); a[2] = di * (ac4.z + di * x4.z);
            di = rsqrtf(d4.w + 1.0f); a[3] = di * (ac4.w + di * x4.w);
            #pragma unroll
            for (int k = 0; k < 4; k++) {
                float t = (a[k] - LUT_MIN) * inv_step;
                t = fminf(fmaxf(t, 0.0f), (float)LUT_N);
                int   idx  = (int)t;
                float frac = t - (float)idx;
                float lo = g_lut[idx];
                float hi = g_lut[idx + 1];
                r[k] = fmaf(hi - lo, frac, lo);
            }
            ((float4*)out)[i] = make_float4(r[0], r[1], r[2], r[3]);
        }
        int base = nvec << 2;
        if (tid < N - base) {
            int i = base + tid;
            float di = rsqrtf(g_deg[i] + 1.0f);
            float a  = di * (g_accum[i] + di * x[i]);
            g_deg[i] = 0.0f;
            g_accum[i] = 0.0f;
            float t = (a - LUT_MIN) * inv_step;
            t = fminf(fmaxf(t, 0.0f), (float)LUT_N);
            int   idx  = (int)t;
            float frac = t - (float)idx;
            float lo = g_lut[idx];
            float hi = g_lut[idx + 1];
            out[i] = fmaf(hi - lo, frac, lo);
        }
    }
}

extern "C" void kernel_launch(void* const* d_in, const int* in_sizes, int n_in,
                              void* d_out, int out_size) {
    const float* x    = (const float*)d_in[0];
    const float* ew   = (const float*)d_in[1];
    const float* Wz   = (const float*)d_in[2];
    const float* bz   = (const float*)d_in[3];
    const float* Lz   = (const float*)d_in[4];
    const float* lbz  = (const float*)d_in[5];
    // d_in[6..9]: Wr, br, Lr, lbr -- dead (H0 = 0 makes H*R = 0)
    const float* Wh   = (const float*)d_in[10];
    const float* bh   = (const float*)d_in[11];
    const float* Lh   = (const float*)d_in[12];
    const float* lbh  = (const float*)d_in[13];
    const float* Wout = (const float*)d_in[14];
    const float* bout = (const float*)d_in[15];
    const int*   eidx = (const int*)d_in[16];

    int N = in_sizes[0];
    int E = in_sizes[1];
    const int* src = eidx;
    const int* dst = eidx + E;
    float* out = (float*)d_out;

    int vec_ok = (((uintptr_t)src & 15) == 0) && (((uintptr_t)dst & 15) == 0) &&
                 (((uintptr_t)ew  & 15) == 0) && (((uintptr_t)x & 15) == 0) &&
                 (((uintptr_t)out & 15) == 0);

    fused_kernel<<<NB, TB>>>(src, dst, ew, x, out, N, E, vec_ok,
                             Wz, bz, Lz, lbz, Wh, bh, Lh, lbh, Wout, bout);
}

// round 8
// speedup vs baseline: 1.0558x; 1.0558x over previous
#include <cuda_runtime.h>
#include <cstdint>

#define N_NODES_MAX 100000
#define HIDDEN 64
#define LUT_N 8192
#define LUT_MIN (-32.0f)
#define LUT_RANGE 64.0f

#define OCC 4
#define NB (148 * OCC)  // exactly one full wave at 4 blocks/SM -> co-resident
#define TB 256

// Scratch. INVARIANT: g_deg and g_accum are all-zero between kernel_launch
// calls (static zero-init; phase D restores both each call).
__device__ float g_deg[N_NODES_MAX];     // zero between calls
__device__ float g_accum[N_NODES_MAX];   // zero between calls
__device__ float g_px[N_NODES_MAX];      // rsqrt(deg+1)*x
__device__ float g_lut[LUT_N + 2];
__device__ unsigned g_bar_count;         // zero between calls (barrier resets it)
__device__ unsigned g_bar_gen;           // monotonic across calls

__device__ __forceinline__ float tanh_approx(float x) {
    float y;
    asm("tanh.approx.f32 %0, %1;" : "=f"(y) : "f"(x));
    return y;
}

// Software grid barrier. Valid because grid == one full resident wave.
__device__ __forceinline__ void grid_barrier() {
    __syncthreads();
    if (threadIdx.x == 0) {
        __threadfence();                              // order my phase's writes
        unsigned gen = *(volatile unsigned*)&g_bar_gen;
        if (atomicAdd(&g_bar_count, 1u) == NB - 1u) {
            g_bar_count = 0u;                         // reset BEFORE release
            __threadfence();
            *(volatile unsigned*)&g_bar_gen = gen + 1u;  // release
        } else {
            while (*(volatile unsigned*)&g_bar_gen == gen) { }
        }
        __threadfence();                              // acquire others' writes
    }
    __syncthreads();
}

__global__ void __launch_bounds__(TB, OCC)
fused_kernel(const int* __restrict__ src, const int* __restrict__ dst,
             const float* __restrict__ ew, const float* __restrict__ x,
             float* __restrict__ out, int N, int E, int vec_ok,
             const float* __restrict__ Wz, const float* __restrict__ bz,
             const float* __restrict__ Lz, const float* __restrict__ lbz,
             const float* __restrict__ Wh, const float* __restrict__ bh,
             const float* __restrict__ Lh, const float* __restrict__ lbh,
             const float* __restrict__ Wout, const float* __restrict__ bout) {
    const int tid = blockIdx.x * TB + threadIdx.x;
    const int NT  = NB * TB;

    // ===================== Phase A: LUT build + degree =====================
    {
        // every block folds the tiny matrices (L2-broadcast, cheap);
        // threads then fill LUT entries.
        __shared__ float s_uz[HIDDEN], s_cz[HIDDEN], s_uh[HIDDEN], s_ch[HIDDEN], s_w[HIDDEN];
        __shared__ float s_b0;
        int j = threadIdx.x;
        if (j < HIDDEN) {
            float uz = 0.f, cz = lbz[j], uh = 0.f, ch = lbh[j];
            #pragma unroll 8
            for (int k = 0; k < HIDDEN; k++) {
                float lz = Lz[k * HIDDEN + j];
                float lh = Lh[k * HIDDEN + j];
                uz = fmaf(Wz[k], lz, uz);
                cz = fmaf(bz[k], lz, cz);
                uh = fmaf(Wh[k], lh, uh);
                ch = fmaf(bh[k], lh, ch);
            }
            s_uz[j] = uz; s_cz[j] = cz; s_uh[j] = uh; s_ch[j] = ch;
            s_w[j] = Wout[j];
        }
        if (j == 0) s_b0 = bout[0];
        __syncthreads();

        if (tid <= LUT_N + 1) {
            const float step = LUT_RANGE / (float)LUT_N;
            float a = LUT_MIN + (float)tid * step;
            float acc = s_b0;
            #pragma unroll 8
            for (int jj = 0; jj < HIDDEN; jj++) {
                float tz = tanh_approx(0.5f * fmaf(a, s_uz[jj], s_cz[jj]));
                float th = tanh_approx(fmaf(a, s_uh[jj], s_ch[jj]));
                float h = fmaxf(0.5f * (1.0f - tz) * th, 0.0f);
                acc = fmaf(h, s_w[jj], acc);
            }
            g_lut[tid] = acc;
        }

        // degree accumulation, 2 quads per iteration (front-batched loads)
        if (vec_ok) {
            int nvec = E >> 2;
            int i = tid;
            while (i + NT < nvec) {
                int4   d0 = ((const int4*)dst)[i];
                int4   d1 = ((const int4*)dst)[i + NT];
                float4 w0 = ((const float4*)ew)[i];
                float4 w1 = ((const float4*)ew)[i + NT];
                atomicAdd(&g_deg[d0.x], w0.x); atomicAdd(&g_deg[d0.y], w0.y);
                atomicAdd(&g_deg[d0.z], w0.z); atomicAdd(&g_deg[d0.w], w0.w);
                atomicAdd(&g_deg[d1.x], w1.x); atomicAdd(&g_deg[d1.y], w1.y);
                atomicAdd(&g_deg[d1.z], w1.z); atomicAdd(&g_deg[d1.w], w1.w);
                i += 2 * NT;
            }
            if (i < nvec) {
                int4   d0 = ((const int4*)dst)[i];
                float4 w0 = ((const float4*)ew)[i];
                atomicAdd(&g_deg[d0.x], w0.x); atomicAdd(&g_deg[d0.y], w0.y);
                atomicAdd(&g_deg[d0.z], w0.z); atomicAdd(&g_deg[d0.w], w0.w);
            }
            int base = nvec << 2;
            if (tid < E - base)
                atomicAdd(&g_deg[dst[base + tid]], ew[base + tid]);
        } else {
            for (int e = tid; e < E; e += NT)
                atomicAdd(&g_deg[dst[e]], ew[e]);
        }
    }
    grid_barrier();

    // ===================== Phase B: px = rsqrt(deg+1)*x ====================
    {
        int nvec = N >> 2;
        for (int i = tid; i < nvec; i += NT) {
            float4 d4 = ((const float4*)g_deg)[i];
            float4 x4 = ((const float4*)x)[i];
            float4 px;
            px.x = rsqrtf(d4.x + 1.0f) * x4.x;
            px.y = rsqrtf(d4.y + 1.0f) * x4.y;
            px.z = rsqrtf(d4.z + 1.0f) * x4.z;
            px.w = rsqrtf(d4.w + 1.0f) * x4.w;
            ((float4*)g_px)[i] = px;
        }
        int base = nvec << 2;
        if (tid < N - base) {
            int i = base + tid;
            g_px[i] = rsqrtf(g_deg[i] + 1.0f) * x[i];
        }
    }
    grid_barrier();

    // ===================== Phase C: normalized scatter ======================
    {
        if (vec_ok) {
            int nvec = E >> 2;
            int i = tid;
            while (i + NT < nvec) {   // 2 quads per iter (6 streaming + 8 gathers)
                int4   s0 = ((const int4*)src)[i];
                int4   s1 = ((const int4*)src)[i + NT];
                int4   d0 = ((const int4*)dst)[i];
                int4   d1 = ((const int4*)dst)[i + NT];
                float4 w0 = ((const float4*)ew)[i];
                float4 w1 = ((const float4*)ew)[i + NT];
                float p00 = __ldg(&g_px[s0.x]), p01 = __ldg(&g_px[s0.y]);
                float p02 = __ldg(&g_px[s0.z]), p03 = __ldg(&g_px[s0.w]);
                float p10 = __ldg(&g_px[s1.x]), p11 = __ldg(&g_px[s1.y]);
                float p12 = __ldg(&g_px[s1.z]), p13 = __ldg(&g_px[s1.w]);
                atomicAdd(&g_accum[d0.x], w0.x * p00);
                atomicAdd(&g_accum[d0.y], w0.y * p01);
                atomicAdd(&g_accum[d0.z], w0.z * p02);
                atomicAdd(&g_accum[d0.w], w0.w * p03);
                atomicAdd(&g_accum[d1.x], w1.x * p10);
                atomicAdd(&g_accum[d1.y], w1.y * p11);
                atomicAdd(&g_accum[d1.z], w1.z * p12);
                atomicAdd(&g_accum[d1.w], w1.w * p13);
                i += 2 * NT;
            }
            if (i < nvec) {
                int4   s0 = ((const int4*)src)[i];
                int4   d0 = ((const int4*)dst)[i];
                float4 w0 = ((const float4*)ew)[i];
                float p00 = __ldg(&g_px[s0.x]), p01 = __ldg(&g_px[s0.y]);
                float p02 = __ldg(&g_px[s0.z]), p03 = __ldg(&g_px[s0.w]);
                atomicAdd(&g_accum[d0.x], w0.x * p00);
                atomicAdd(&g_accum[d0.y], w0.y * p01);
                atomicAdd(&g_accum[d0.z], w0.z * p02);
                atomicAdd(&g_accum[d0.w], w0.w * p03);
            }
            int base = nvec << 2;
            if (tid < E - base) {
                int e = base + tid;
                atomicAdd(&g_accum[dst[e]], ew[e] * __ldg(&g_px[src[e]]));
            }
        } else {
            for (int e = tid; e < E; e += NT)
                atomicAdd(&g_accum[dst[e]], ew[e] * __ldg(&g_px[src[e]]));
        }
    }
    grid_barrier();

    // ============ Phase D: LUT epilogue; reset g_deg & g_accum =============
    {
        const float inv_step = (float)LUT_N / LUT_RANGE;
        const float4 z4 = make_float4(0.f, 0.f, 0.f, 0.f);
        int nvec = N >> 2;
        for (int i = tid; i < nvec; i += NT) {
            float4 d4  = ((const float4*)g_deg)[i];
            float4 ac4 = ((const float4*)g_accum)[i];
            float4 x4  = ((const float4*)x)[i];
            ((float4*)g_deg)[i]   = z4;     // restore invariant
            ((float4*)g_accum)[i] = z4;     // restore invariant
            float a[4], r[4];
            float di;
            di = rsqrtf(d4.x + 1.0f); a[0] = di * (ac4.x + di * x4.x);
            di = rsqrtf(d4.y + 1.0f); a[1] = di * (ac4.y + di * x4.y);
            di = rsqrtf(d4.z + 1.0f); a[2] = di * (ac4.z + di * x4.z);
            di = rsqrtf(d4.w + 1.0f); a[3] = di * (ac4.w + di * x4.w);
            #pragma unroll
            for (int k = 0; k < 4; k++) {
                float t = (a[k] - LUT_MIN) * inv_step;
                t = fminf(fmaxf(t, 0.0f), (float)LUT_N);
                int   idx  = (int)t;
                float frac = t - (float)idx;
                float lo = g_lut[idx];
                float hi = g_lut[idx + 1];
                r[k] = fmaf(hi - lo, frac, lo);
            }
            ((float4*)out)[i] = make_float4(r[0], r[1], r[2], r[3]);
        }
        int base = nvec << 2;
        if (tid < N - base) {
            int i = base + tid;
            float di = rsqrtf(g_deg[i] + 1.0f);
            float a  = di * (g_accum[i] + di * x[i]);
            g_deg[i] = 0.0f;
            g_accum[i] = 0.0f;
            float t = (a - LUT_MIN) * inv_step;
            t = fminf(fmaxf(t, 0.0f), (float)LUT_N);
            int   idx  = (int)t;
            float frac = t - (float)idx;
            float lo = g_lut[idx];
            float hi = g_lut[idx + 1];
            out[i] = fmaf(hi - lo, frac, lo);
        }
    }
}

extern "C" void kernel_launch(void* const* d_in, const int* in_sizes, int n_in,
                              void* d_out, int out_size) {
    const float* x    = (const float*)d_in[0];
    const float* ew   = (const float*)d_in[1];
    const float* Wz   = (const float*)d_in[2];
    const float* bz   = (const float*)d_in[3];
    const float* Lz   = (const float*)d_in[4];
    const float* lbz  = (const float*)d_in[5];
    // d_in[6..9]: Wr, br, Lr, lbr -- dead (H0 = 0 makes H*R = 0)
    const float* Wh   = (const float*)d_in[10];
    const float* bh   = (const float*)d_in[11];
    const float* Lh   = (const float*)d_in[12];
    const float* lbh  = (const float*)d_in[13];
    const float* Wout = (const float*)d_in[14];
    const float* bout = (const float*)d_in[15];
    const int*   eidx = (const int*)d_in[16];

    int N = in_sizes[0];
    int E = in_sizes[1];
    const int* src = eidx;
    const int* dst = eidx + E;
    float* out = (float*)d_out;

    int vec_ok = (((uintptr_t)src & 15) == 0) && (((uintptr_t)dst & 15) == 0) &&
                 (((uintptr_t)ew  & 15) == 0) && (((uintptr_t)x & 15) == 0) &&
                 (((uintptr_t)out & 15) == 0);

    fused_kernel<<<NB, TB>>>(src, dst, ew, x, out, N, E, vec_ok,
                             Wz, bz, Lz, lbz, Wh, bh, Lh, lbh, Wout, bout);
}

// round 9
// speedup vs baseline: 1.0651x; 1.0088x over previous
#include <cuda_runtime.h>
#include <cstdint>

#define N_NODES_MAX 100000
#define HIDDEN 64
#define LUT_N 8192
#define LUT_MIN (-32.0f)
#define LUT_RANGE 64.0f

#define OCC 2
#define NB (148 * OCC)  // exactly one full wave at 2 blocks/SM -> co-resident
#define TB 256

// Scratch. INVARIANT: g_deg and g_accum are all-zero between kernel_launch
// calls (static zero-init; phase D restores both each call).
__device__ float g_deg[N_NODES_MAX];     // zero between calls
__device__ float g_accum[N_NODES_MAX];   // zero between calls
__device__ float g_px[N_NODES_MAX];      // rsqrt(deg+1)*x
__device__ float g_lut[LUT_N + 2];
__device__ unsigned g_bar_count;         // zero between calls (barrier resets it)
__device__ unsigned g_bar_gen;           // monotonic across calls

__device__ __forceinline__ float tanh_approx(float x) {
    float y;
    asm("tanh.approx.f32 %0, %1;" : "=f"(y) : "f"(x));
    return y;
}

// Software grid barrier. Valid because grid == one full resident wave.
__device__ __forceinline__ void grid_barrier() {
    __syncthreads();
    if (threadIdx.x == 0) {
        __threadfence();                              // order my phase's writes
        unsigned gen = *(volatile unsigned*)&g_bar_gen;
        if (atomicAdd(&g_bar_count, 1u) == NB - 1u) {
            g_bar_count = 0u;                         // reset BEFORE release
            __threadfence();
            *(volatile unsigned*)&g_bar_gen = gen + 1u;  // release
        } else {
            while (*(volatile unsigned*)&g_bar_gen == gen) { }
        }
        __threadfence();                              // acquire others' writes
    }
    __syncthreads();
}

__global__ void __launch_bounds__(TB, OCC)
fused_kernel(const int* __restrict__ src, const int* __restrict__ dst,
             const float* __restrict__ ew, const float* __restrict__ x,
             float* __restrict__ out, int N, int E, int vec_ok,
             const float* __restrict__ Wz, const float* __restrict__ bz,
             const float* __restrict__ Lz, const float* __restrict__ lbz,
             const float* __restrict__ Wh, const float* __restrict__ bh,
             const float* __restrict__ Lh, const float* __restrict__ lbh,
             const float* __restrict__ Wout, const float* __restrict__ bout) {
    const int tid = blockIdx.x * TB + threadIdx.x;
    const int NT  = NB * TB;

    // ===================== Phase A: LUT build + degree =====================
    {
        __shared__ float s_uz[HIDDEN], s_cz[HIDDEN], s_uh[HIDDEN], s_ch[HIDDEN], s_w[HIDDEN];
        __shared__ float s_b0;
        int j = threadIdx.x;
        if (j < HIDDEN) {
            float uz = 0.f, cz = lbz[j], uh = 0.f, ch = lbh[j];
            #pragma unroll 8
            for (int k = 0; k < HIDDEN; k++) {
                float lz = Lz[k * HIDDEN + j];
                float lh = Lh[k * HIDDEN + j];
                uz = fmaf(Wz[k], lz, uz);
                cz = fmaf(bz[k], lz, cz);
                uh = fmaf(Wh[k], lh, uh);
                ch = fmaf(bh[k], lh, ch);
            }
            s_uz[j] = uz; s_cz[j] = cz; s_uh[j] = uh; s_ch[j] = ch;
            s_w[j] = Wout[j];
        }
        if (j == 0) s_b0 = bout[0];
        __syncthreads();

        // LUT entries (8194 total; NT = 75776 threads -> at most 1 each)
        if (tid <= LUT_N + 1) {
            const float step = LUT_RANGE / (float)LUT_N;
            float a = LUT_MIN + (float)tid * step;
            float acc = s_b0;
            #pragma unroll 8
            for (int jj = 0; jj < HIDDEN; jj++) {
                float tz = tanh_approx(0.5f * fmaf(a, s_uz[jj], s_cz[jj]));
                float th = tanh_approx(fmaf(a, s_uh[jj], s_ch[jj]));
                float h = fmaxf(0.5f * (1.0f - tz) * th, 0.0f);
                acc = fmaf(h, s_w[jj], acc);
            }
            g_lut[tid] = acc;
        }

        // degree accumulation: 4 quads front-batched per iteration (MLP_p1 = 8)
        if (vec_ok) {
            int nvec = E >> 2;
            int i = tid;
            while (i + 3 * NT < nvec) {
                int4   d0 = ((const int4*)dst)[i];
                int4   d1 = ((const int4*)dst)[i + NT];
                int4   d2 = ((const int4*)dst)[i + 2 * NT];
                int4   d3 = ((const int4*)dst)[i + 3 * NT];
                float4 w0 = ((const float4*)ew)[i];
                float4 w1 = ((const float4*)ew)[i + NT];
                float4 w2 = ((const float4*)ew)[i + 2 * NT];
                float4 w3 = ((const float4*)ew)[i + 3 * NT];
                atomicAdd(&g_deg[d0.x], w0.x); atomicAdd(&g_deg[d0.y], w0.y);
                atomicAdd(&g_deg[d0.z], w0.z); atomicAdd(&g_deg[d0.w], w0.w);
                atomicAdd(&g_deg[d1.x], w1.x); atomicAdd(&g_deg[d1.y], w1.y);
                atomicAdd(&g_deg[d1.z], w1.z); atomicAdd(&g_deg[d1.w], w1.w);
                atomicAdd(&g_deg[d2.x], w2.x); atomicAdd(&g_deg[d2.y], w2.y);
                atomicAdd(&g_deg[d2.z], w2.z); atomicAdd(&g_deg[d2.w], w2.w);
                atomicAdd(&g_deg[d3.x], w3.x); atomicAdd(&g_deg[d3.y], w3.y);
                atomicAdd(&g_deg[d3.z], w3.z); atomicAdd(&g_deg[d3.w], w3.w);
                i += 4 * NT;
            }
            while (i < nvec) {
                int4   d0 = ((const int4*)dst)[i];
                float4 w0 = ((const float4*)ew)[i];
                atomicAdd(&g_deg[d0.x], w0.x); atomicAdd(&g_deg[d0.y], w0.y);
                atomicAdd(&g_deg[d0.z], w0.z); atomicAdd(&g_deg[d0.w], w0.w);
                i += NT;
            }
            int base = nvec << 2;
            if (tid < E - base)
                atomicAdd(&g_deg[dst[base + tid]], ew[base + tid]);
        } else {
            for (int e = tid; e < E; e += NT)
                atomicAdd(&g_deg[dst[e]], ew[e]);
        }
    }
    grid_barrier();

    // ===================== Phase B: px = rsqrt(deg+1)*x ====================
    {
        int nvec = N >> 2;
        for (int i = tid; i < nvec; i += NT) {
            float4 d4 = ((const float4*)g_deg)[i];
            float4 x4 = ((const float4*)x)[i];
            float4 px;
            px.x = rsqrtf(d4.x + 1.0f) * x4.x;
            px.y = rsqrtf(d4.y + 1.0f) * x4.y;
            px.z = rsqrtf(d4.z + 1.0f) * x4.z;
            px.w = rsqrtf(d4.w + 1.0f) * x4.w;
            ((float4*)g_px)[i] = px;
        }
        int base = nvec << 2;
        if (tid < N - base) {
            int i = base + tid;
            g_px[i] = rsqrtf(g_deg[i] + 1.0f) * x[i];
        }
    }
    grid_barrier();

    // ===================== Phase C: normalized scatter ======================
    {
        if (vec_ok) {
            int nvec = E >> 2;
            int i = tid;
            while (i + 3 * NT < nvec) {   // 12 vec loads + 16 gathers in flight
                int4   s0 = ((const int4*)src)[i];
                int4   s1 = ((const int4*)src)[i + NT];
                int4   s2 = ((const int4*)src)[i + 2 * NT];
                int4   s3 = ((const int4*)src)[i + 3 * NT];
                int4   d0 = ((const int4*)dst)[i];
                int4   d1 = ((const int4*)dst)[i + NT];
                int4   d2 = ((const int4*)dst)[i + 2 * NT];
                int4   d3 = ((const int4*)dst)[i + 3 * NT];
                float4 w0 = ((const float4*)ew)[i];
                float4 w1 = ((const float4*)ew)[i + NT];
                float4 w2 = ((const float4*)ew)[i + 2 * NT];
                float4 w3 = ((const float4*)ew)[i + 3 * NT];
                float p00 = __ldg(&g_px[s0.x]), p01 = __ldg(&g_px[s0.y]);
                float p02 = __ldg(&g_px[s0.z]), p03 = __ldg(&g_px[s0.w]);
                float p10 = __ldg(&g_px[s1.x]), p11 = __ldg(&g_px[s1.y]);
                float p12 = __ldg(&g_px[s1.z]), p13 = __ldg(&g_px[s1.w]);
                float p20 = __ldg(&g_px[s2.x]), p21 = __ldg(&g_px[s2.y]);
                float p22 = __ldg(&g_px[s2.z]), p23 = __ldg(&g_px[s2.w]);
                float p30 = __ldg(&g_px[s3.x]), p31 = __ldg(&g_px[s3.y]);
                float p32 = __ldg(&g_px[s3.z]), p33 = __ldg(&g_px[s3.w]);
                atomicAdd(&g_accum[d0.x], w0.x * p00);
                atomicAdd(&g_accum[d0.y], w0.y * p01);
                atomicAdd(&g_accum[d0.z], w0.z * p02);
                atomicAdd(&g_accum[d0.w], w0.w * p03);
                atomicAdd(&g_accum[d1.x], w1.x * p10);
                atomicAdd(&g_accum[d1.y], w1.y * p11);
                atomicAdd(&g_accum[d1.z], w1.z * p12);
                atomicAdd(&g_accum[d1.w], w1.w * p13);
                atomicAdd(&g_accum[d2.x], w2.x * p20);
                atomicAdd(&g_accum[d2.y], w2.y * p21);
                atomicAdd(&g_accum[d2.z], w2.z * p22);
                atomicAdd(&g_accum[d2.w], w2.w * p23);
                atomicAdd(&g_accum[d3.x], w3.x * p30);
                atomicAdd(&g_accum[d3.y], w3.y * p31);
                atomicAdd(&g_accum[d3.z], w3.z * p32);
                atomicAdd(&g_accum[d3.w], w3.w * p33);
                i += 4 * NT;
            }
            while (i < nvec) {
                int4   s0 = ((const int4*)src)[i];
                int4   d0 = ((const int4*)dst)[i];
                float4 w0 = ((const float4*)ew)[i];
                float p00 = __ldg(&g_px[s0.x]), p01 = __ldg(&g_px[s0.y]);
                float p02 = __ldg(&g_px[s0.z]), p03 = __ldg(&g_px[s0.w]);
                atomicAdd(&g_accum[d0.x], w0.x * p00);
                atomicAdd(&g_accum[d0.y], w0.y * p01);
                atomicAdd(&g_accum[d0.z], w0.z * p02);
                atomicAdd(&g_accum[d0.w], w0.w * p03);
                i += NT;
            }
            int base = nvec << 2;
            if (tid < E - base) {
                int e = base + tid;
                atomicAdd(&g_accum[dst[e]], ew[e] * __ldg(&g_px[src[e]]));
            }
        } else {
            for (int e = tid; e < E; e += NT)
                atomicAdd(&g_accum[dst[e]], ew[e] * __ldg(&g_px[src[e]]));
        }
    }
    grid_barrier();

    // ============ Phase D: LUT epilogue; reset g_deg & g_accum =============
    {
        const float inv_step = (float)LUT_N / LUT_RANGE;
        const float4 z4 = make_float4(0.f, 0.f, 0.f, 0.f);
        int nvec = N >> 2;
        for (int i = tid; i < nvec; i += NT) {
            float4 d4  = ((const float4*)g_deg)[i];
            float4 ac4 = ((const float4*)g_accum)[i];
            float4 x4  = ((const float4*)x)[i];
            ((float4*)g_deg)[i]   = z4;     // restore invariant
            ((float4*)g_accum)[i] = z4;     // restore invariant
            float a[4], r[4];
            float di;
            di = rsqrtf(d4.x + 1.0f); a[0] = di * (ac4.x + di * x4.x);
            di = rsqrtf(d4.y + 1.0f); a[1] = di * (ac4.y + di * x4.y);
            di = rsqrtf(d4.z + 1.0f); a[2] = di * (ac4.z + di * x4.z);
            di = rsqrtf(d4.w + 1.0f); a[3] = di * (ac4.w + di * x4.w);
            #pragma unroll
            for (int k = 0; k < 4; k++) {
                float t = (a[k] - LUT_MIN) * inv_step;
                t = fminf(fmaxf(t, 0.0f), (float)LUT_N);
                int   idx  = (int)t;
                float frac = t - (float)idx;
                float lo = g_lut[idx];
                float hi = g_lut[idx + 1];
                r[k] = fmaf(hi - lo, frac, lo);
            }
            ((float4*)out)[i] = make_float4(r[0], r[1], r[2], r[3]);
        }
        int base = nvec << 2;
        if (tid < N - base) {
            int i = base + tid;
            float di = rsqrtf(g_deg[i] + 1.0f);
            float a  = di * (g_accum[i] + di * x[i]);
            g_deg[i] = 0.0f;
            g_accum[i] = 0.0f;
            float t = (a - LUT_MIN) * inv_step;
            t = fminf(fmaxf(t, 0.0f), (float)LUT_N);
            int   idx  = (int)t;
            float frac = t - (float)idx;
            float lo = g_lut[idx];
            float hi = g_lut[idx + 1];
            out[i] = fmaf(hi - lo, frac, lo);
        }
    }
}

extern "C" void kernel_launch(void* const* d_in, const int* in_sizes, int n_in,
                              void* d_out, int out_size) {
    const float* x    = (const float*)d_in[0];
    const float* ew   = (const float*)d_in[1];
    const float* Wz   = (const float*)d_in[2];
    const float* bz   = (const float*)d_in[3];
    const float* Lz   = (const float*)d_in[4];
    const float* lbz  = (const float*)d_in[5];
    // d_in[6..9]: Wr, br, Lr, lbr -- dead (H0 = 0 makes H*R = 0)
    const float* Wh   = (const float*)d_in[10];
    const float* bh   = (const float*)d_in[11];
    const float* Lh   = (const float*)d_in[12];
    const float* lbh  = (const float*)d_in[13];
    const float* Wout = (const float*)d_in[14];
    const float* bout = (const float*)d_in[15];
    const int*   eidx = (const int*)d_in[16];

    int N = in_sizes[0];
    int E = in_sizes[1];
    const int* src = eidx;
    const int* dst = eidx + E;
    float* out = (float*)d_out;

    int vec_ok = (((uintptr_t)src & 15) == 0) && (((uintptr_t)dst & 15) == 0) &&
                 (((uintptr_t)ew  & 15) == 0) && (((uintptr_t)x & 15) == 0) &&
                 (((uintptr_t)out & 15) == 0);

    fused_kernel<<<NB, TB>>>(src, dst, ew, x, out, N, E, vec_ok,
                             Wz, bz, Lz, lbz, Wh, bh, Lh, lbh, Wout, bout);
}

// round 10
// speedup vs baseline: 1.2744x; 1.1964x over previous
#include <cuda_runtime.h>
#include <cstdint>

#define N_NODES_MAX 100000
#define HIDDEN 64
#define LUT_N 8192
#define LUT_MIN (-32.0f)
#define LUT_RANGE 64.0f

// Scratch. INVARIANT: g_deg and g_accum are all-zero between kernel_launch
// calls (static zero-init; out_kernel restores both each call).
__device__ float g_deg[N_NODES_MAX];     // zero between calls
__device__ float g_accum[N_NODES_MAX];   // zero between calls
__device__ float g_px[N_NODES_MAX];      // rsqrt(deg+1)*x
__device__ float g_lut[LUT_N + 2];

__device__ __forceinline__ float tanh_approx(float x) {
    float y;
    asm("tanh.approx.f32 %0, %1;" : "=f"(y) : "f"(x));
    return y;
}

// ---------------------------------------------------------------------------
// Pass 1 over edges: degree accumulation. Blocks < 32 additionally build the
// g(a) LUT (each re-folds the tiny matrices independently).
// Streaming loads use __ldlu (last-use) to avoid evicting the resident
// g_deg/g_accum/g_px working set from L2.
// ---------------------------------------------------------------------------
__global__ void deg_kernel(const int* __restrict__ dst, const float* __restrict__ ew,
                           int E, int vec_ok,
                           const float* __restrict__ Wz, const float* __restrict__ bz,
                           const float* __restrict__ Lz, const float* __restrict__ lbz,
                           const float* __restrict__ Wh, const float* __restrict__ bh,
                           const float* __restrict__ Lh, const float* __restrict__ lbh,
                           const float* __restrict__ Wout, const float* __restrict__ bout) {
    int lutBlocks = gridDim.x < 32 ? (int)gridDim.x : 32;
    __shared__ float s_uz[HIDDEN], s_cz[HIDDEN], s_uh[HIDDEN], s_ch[HIDDEN], s_w[HIDDEN];
    __shared__ float s_b0;
    if (blockIdx.x < (unsigned)lutBlocks) {
        int j = threadIdx.x;
        if (j < HIDDEN) {
            float uz = 0.f, cz = lbz[j], uh = 0.f, ch = lbh[j];
            #pragma unroll 8
            for (int k = 0; k < HIDDEN; k++) {
                float lz = Lz[k * HIDDEN + j];
                float lh = Lh[k * HIDDEN + j];
                uz = fmaf(Wz[k], lz, uz);
                cz = fmaf(bz[k], lz, cz);
                uh = fmaf(Wh[k], lh, uh);
                ch = fmaf(bh[k], lh, ch);
            }
            s_uz[j] = uz; s_cz[j] = cz; s_uh[j] = uh; s_ch[j] = ch;
            s_w[j] = Wout[j];
        }
        if (j == 0) s_b0 = bout[0];
        __syncthreads();
        const float step = LUT_RANGE / (float)LUT_N;
        for (int entry = blockIdx.x * blockDim.x + threadIdx.x;
             entry <= LUT_N + 1; entry += lutBlocks * blockDim.x) {
            float a = LUT_MIN + (float)entry * step;
            float acc = s_b0;
            #pragma unroll 8
            for (int jj = 0; jj < HIDDEN; jj++) {
                float tz = tanh_approx(0.5f * fmaf(a, s_uz[jj], s_cz[jj]));
                float th = tanh_approx(fmaf(a, s_uh[jj], s_ch[jj]));
                float h = fmaxf(0.5f * (1.0f - tz) * th, 0.0f);
                acc = fmaf(h, s_w[jj], acc);
            }
            g_lut[entry] = acc;
        }
    }

    // edge work: 4 quads per thread, loads front-batched (MLP_p1 = 8)
    int tid = blockIdx.x * blockDim.x + threadIdx.x;
    int NT  = gridDim.x * blockDim.x;
    if (vec_ok) {
        int nvec = E >> 2;
        int4 d4[4]; float4 w4[4]; bool v[4];
        #pragma unroll
        for (int k = 0; k < 4; k++) {
            int i = tid + k * NT;
            v[k] = (i < nvec);
            if (v[k]) {
                d4[k] = __ldlu(&((const int4*)dst)[i]);
                w4[k] = __ldlu(&((const float4*)ew)[i]);
            }
        }
        #pragma unroll
        for (int k = 0; k < 4; k++) {
            if (v[k]) {
                atomicAdd(&g_deg[d4[k].x], w4[k].x);
                atomicAdd(&g_deg[d4[k].y], w4[k].y);
                atomicAdd(&g_deg[d4[k].z], w4[k].z);
                atomicAdd(&g_deg[d4[k].w], w4[k].w);
            }
        }
        int base = nvec << 2;
        if (tid < E - base)
            atomicAdd(&g_deg[dst[base + tid]], ew[base + tid]);
    } else {
        for (int e = tid; e < E; e += NT)
            atomicAdd(&g_deg[dst[e]], ew[e]);
    }
}

// ---------------------------------------------------------------------------
// px = rsqrt(deg+1)*x. Does NOT reset g_deg (out_kernel recomputes dinv).
// ---------------------------------------------------------------------------
__global__ void dinv_kernel(const float* __restrict__ x, int n) {
    int i = blockIdx.x * blockDim.x + threadIdx.x;
    int nvec = n >> 2;
    if (i < nvec) {
        float4 d4 = ((const float4*)g_deg)[i];
        float4 x4 = ((const float4*)x)[i];
        float4 px;
        px.x = rsqrtf(d4.x + 1.0f) * x4.x;
        px.y = rsqrtf(d4.y + 1.0f) * x4.y;
        px.z = rsqrtf(d4.z + 1.0f) * x4.z;
        px.w = rsqrtf(d4.w + 1.0f) * x4.w;
        ((float4*)g_px)[i] = px;
    }
    int tail = n - (nvec << 2);
    if (i < tail) {
        int j = (nvec << 2) + i;
        g_px[j] = rsqrtf(g_deg[j] + 1.0f) * x[j];
    }
}

// ---------------------------------------------------------------------------
// Pass 2 over edges: normalized scatter-add. 4 quads/thread, front-batched.
// ---------------------------------------------------------------------------
__global__ void agg_kernel(const int* __restrict__ src, const int* __restrict__ dst,
                           const float* __restrict__ ew, int E, int vec_ok) {
    int tid = blockIdx.x * blockDim.x + threadIdx.x;
    int NT  = gridDim.x * blockDim.x;
    if (vec_ok) {
        int nvec = E >> 2;
        int4 s4[4], d4[4]; float4 w4[4]; bool v[4];
        #pragma unroll
        for (int k = 0; k < 4; k++) {
            int i = tid + k * NT;
            v[k] = (i < nvec);
            if (v[k]) {
                s4[k] = __ldlu(&((const int4*)src)[i]);
                d4[k] = __ldlu(&((const int4*)dst)[i]);
                w4[k] = __ldlu(&((const float4*)ew)[i]);
            }
        }
        float p[4][4];
        #pragma unroll
        for (int k = 0; k < 4; k++) {
            if (v[k]) {
                p[k][0] = __ldg(&g_px[s4[k].x]);
                p[k][1] = __ldg(&g_px[s4[k].y]);
                p[k][2] = __ldg(&g_px[s4[k].z]);
                p[k][3] = __ldg(&g_px[s4[k].w]);
            }
        }
        #pragma unroll
        for (int k = 0; k < 4; k++) {
            if (v[k]) {
                atomicAdd(&g_accum[d4[k].x], w4[k].x * p[k][0]);
                atomicAdd(&g_accum[d4[k].y], w4[k].y * p[k][1]);
                atomicAdd(&g_accum[d4[k].z], w4[k].z * p[k][2]);
                atomicAdd(&g_accum[d4[k].w], w4[k].w * p[k][3]);
            }
        }
        int base = nvec << 2;
        if (tid < E - base) {
            int e = base + tid;
            atomicAdd(&g_accum[dst[e]], ew[e] * __ldg(&g_px[src[e]]));
        }
    } else {
        for (int e = tid; e < E; e += NT)
            atomicAdd(&g_accum[dst[e]], ew[e] * __ldg(&g_px[src[e]]));
    }
}

// ---------------------------------------------------------------------------
// Epilogue via LUT; scalar (1 node/thread, max threads for latency hiding);
// resets g_deg and g_accum (zero invariant). Output via write-through store.
// ---------------------------------------------------------------------------
__global__ void out_kernel(const float* __restrict__ x, float* __restrict__ out, int n) {
    const float inv_step = (float)LUT_N / LUT_RANGE;
    int i = blockIdx.x * blockDim.x + threadIdx.x;
    if (i < n) {
        float d  = g_deg[i];
        float ac = g_accum[i];
        float xv = x[i];
        g_deg[i]   = 0.0f;              // restore invariant
        g_accum[i] = 0.0f;              // restore invariant
        float di = rsqrtf(d + 1.0f);
        float a  = di * (ac + di * xv);
        float t = (a - LUT_MIN) * inv_step;
        t = fminf(fmaxf(t, 0.0f), (float)LUT_N);
        int   idx  = (int)t;
        float frac = t - (float)idx;
        float lo = g_lut[idx];
        float hi = g_lut[idx + 1];
        __stwt(&out[i], fmaf(hi - lo, frac, lo));
    }
}

extern "C" void kernel_launch(void* const* d_in, const int* in_sizes, int n_in,
                              void* d_out, int out_size) {
    const float* x    = (const float*)d_in[0];
    const float* ew   = (const float*)d_in[1];
    const float* Wz   = (const float*)d_in[2];
    const float* bz   = (const float*)d_in[3];
    const float* Lz   = (const float*)d_in[4];
    const float* lbz  = (const float*)d_in[5];
    // d_in[6..9]: Wr, br, Lr, lbr -- dead (H0 = 0 makes H*R = 0)
    const float* Wh   = (const float*)d_in[10];
    const float* bh   = (const float*)d_in[11];
    const float* Lh   = (const float*)d_in[12];
    const float* lbh  = (const float*)d_in[13];
    const float* Wout = (const float*)d_in[14];
    const float* bout = (const float*)d_in[15];
    const int*   eidx = (const int*)d_in[16];

    int N = in_sizes[0];
    int E = in_sizes[1];
    const int* src = eidx;
    const int* dst = eidx + E;
    float* out = (float*)d_out;

    int vec_ok = (((uintptr_t)src & 15) == 0) && (((uintptr_t)dst & 15) == 0) &&
                 (((uintptr_t)ew  & 15) == 0) && (((uintptr_t)x & 15) == 0);

    const int TB = 256;
    int nb_e;
    if (vec_ok) {
        int nvec = E >> 2;
        int nthreads = (nvec + 3) / 4;            // 4 quads per thread
        nb_e = (nthreads + TB - 1) / TB;
        if (nb_e < 1) nb_e = 1;
    } else {
        nb_e = 592;
    }

    // dinv: float4 pass, TB=128 for >=1 block/SM
    const int TBD = 128;
    int nb_d;
    if (vec_ok) {
        int nvec_n = (N + 3) >> 2;
        nb_d = (nvec_n + TBD - 1) / TBD;
        if (nb_d < 1) nb_d = 1;
    } else {
        nb_d = (N + TBD - 1) / TBD;
    }

    int nb_o = (N + TB - 1) / TB;                 // scalar epilogue, 1 node/thread

    deg_kernel<<<nb_e, TB>>>(dst, ew, E, vec_ok, Wz, bz, Lz, lbz,
                             Wh, bh, Lh, lbh, Wout, bout);
    dinv_kernel<<<nb_d, TBD>>>(x, N);
    agg_kernel<<<nb_e, TB>>>(src, dst, ew, E, vec_ok);
    out_kernel<<<nb_o, TB>>>(x, out, N);
}